// round 14
// baseline (speedup 1.0000x reference)
#include <cuda_runtime.h>
#include <math.h>

// LDSMIXTURELQR: sequential nonlinear scan, T=131072 steps.
// 4-warp specialization (128 threads):
//   warp0 lane0   : serial core — affine y-update, stores {y0,y1,n1,th} per step
//   warp0 lanes1+ : idle (exit after init barrier) — branch guards MUST exclude them
//   warp1         : producer — GMEM -> SMEM rings: -xs1, {Q,P}=dt*{qh,m}, raw {qh,m}
//   warp2         : lane0 reconstructs x from n1 (serial fmaf chain) + STG;
//                   lanes 1-31 copy y SMEM -> GMEM (32-bit: odd base offset)
//   warp3         : lane-parallel EXACT u: u = fmaf(th, fmaf(-d,y,qh), fmaf(-c,y,m))
//
// BUG HISTORY: R12/R13 used a bare `else` for warp3, so warp0 lanes 1-31 ran a
// phantom warp3 that raced the ring and clobbered `us`. Branch must be
// `else if (wid == 3)`.
//
// Serial-core algebra (exact identity):
//   y' = a*y + r ;  a = k1 + mdd*th ;  r = th*Q + P
//     k1 = 1 - dt*(g1+g2)/2, mdd = -dt*(g1-g2)/2, Q = dt*qh, P = dt*m
//   n1 = |y - xs1| ;  hn' = fmaf(s/2, n1, A*hn) ;  th = tanh(hn)
//
// NOTE: y_full at out+(T+1), us at out+3(T+1) — ODD float offsets: 32-bit
// stores only in those regions.

#define CH    256
#define NSLOT 4

__device__ __forceinline__ float sqrta(float x) {
    float r; asm("sqrt.approx.f32 %0,%1;" : "=f"(r) : "f"(x)); return r;
}
__device__ __forceinline__ float tanha(float x) {
    float r; asm("tanh.approx.f32 %0,%1;" : "=f"(r) : "f"(x)); return r;
}

__global__ void __launch_bounds__(128, 1) LDSMIXTURELQR_58445914964044_kernel(
    const float* __restrict__ xs1, const float* __restrict__ xs2,
    const float* __restrict__ init_y, const float* __restrict__ x0p,
    const float* __restrict__ Ap, const float* __restrict__ Bp,
    const float* __restrict__ g1p, const float* __restrict__ g2p,
    float* __restrict__ out, int T)
{
    // Order matters: consumer prefetch overreads past row ends; they must land
    // inside the shared block (the next array), never OOB.
    __shared__ __align__(16) float s_nx1[NSLOT][CH * 2];   // -xs1 pairs
    __shared__ __align__(16) float s_qp [NSLOT][CH * 4];   // {Q0,Q1,P0,P1} (dt-scaled)
    __shared__ __align__(16) float s_qm [NSLOT][CH * 4];   // {qh0,qh1,m0,m1} (raw)
    __shared__ __align__(16) float s_out[NSLOT][CH * 4];   // {y0,y1,n1,th}
    __shared__ volatile int f_in_ready[NSLOT];
    __shared__ volatile int f_in_done[NSLOT];
    __shared__ volatile int f_out_ready[NSLOT];
    __shared__ volatile int f_done2[NSLOT];
    __shared__ volatile int f_done3[NSLOT];

    const int tid = threadIdx.x;
    if (tid < NSLOT) {
        f_in_ready[tid] = 0; f_in_done[tid] = 0;
        f_out_ready[tid] = 0; f_done2[tid] = 0; f_done3[tid] = 0;
    }
    __syncthreads();

    const int nchunk = (T + CH - 1) / CH;
    const int wid = tid >> 5;
    const int lane = tid & 31;

    if (tid == 0) {
        // ---------------- serial core (all scalar, 11 FMA-pipe ops) ----------
        float x  = *x0p;
        float y0 = init_y[0], y1 = init_y[1];
        float A_ = *Ap;
        float s_ = Bp[0] + Bp[1];
        float g1 = *g1p, g2 = *g2p;
        const float dt  = 1.0f / 60.0f;
        const float hS  = 0.5f * s_;
        const float qg1 = 0.5f * dt * g1;
        const float qg2 = 0.5f * dt * g2;
        const float k1  = 1.0f - (qg1 + qg2);    // 1 - dt*c
        const float mdd = qg2 - qg1;             // -dt*d

        float xc0 = fminf(fmaxf(x, -10.0f), 10.0f);
        float w0  = 1.0f / (1.0f + expf(-xc0));
        float th  = 2.0f * w0 - 1.0f;            // tanh(x0/2)
        float ah  = 0.5f * (A_ * x);             // A*(x/2)

        for (int c = 0; c < nchunk; c++) {
            const int slot = c & (NSLOT - 1);
            while (f_in_ready[slot] < c + 1) {}
            if (c >= NSLOT) {
                const int need = c - NSLOT + 1;
                while (f_done2[slot] < need) {}
                while (f_done3[slot] < need) {}
            }
            __threadfence_block();

            const int len = min(CH, T - c * CH);
            const float2* pnx = (const float2*)s_nx1[slot];
            const float4* pqp = (const float4*)s_qp[slot];
            float4*       po  = (float4*)s_out[slot];

            if (len == CH) {
                // distance-2 prefetch (overreads land in adjacent SMEM: safe)
                float2 a_nx = pnx[0]; float4 a_qp = pqp[0];
                float2 b_nx = pnx[1]; float4 b_qp = pqp[1];

                #pragma unroll 16
                for (int i = 0; i < CH; i++) {
                    const float2 nx = a_nx;   // {-xs1_0, -xs1_1}
                    const float4 qp = a_qp;   // {Q0, Q1, P0, P1}
                    a_nx = b_nx; a_qp = b_qp;
                    b_nx = pnx[i + 2];
                    b_qp = pqp[i + 2];

                    // e1_i = y_i - xs1_i ; n1 = |e1|
                    const float e1lo = y0 + nx.x;
                    const float e1hi = y1 + nx.y;
                    const float hh = e1hi * e1hi;
                    const float sq = fmaf(e1lo, e1lo, hh);
                    const float n1 = sqrta(sq);
                    const float hn = fmaf(hS, n1, ah);   // x_{i+1}/2
                    ah = A_ * hn;

                    // affine y-update: y' = a*y + r (uses th_i)
                    const float thi = th;
                    const float aco = fmaf(mdd, thi, k1);
                    const float r0  = fmaf(thi, qp.x, qp.z);
                    const float r1  = fmaf(thi, qp.y, qp.w);

                    th = tanha(hn);                      // th_{i+1}

                    y0 = fmaf(y0, aco, r0);
                    y1 = fmaf(y1, aco, r1);

                    float4 st; st.x = y0; st.y = y1; st.z = n1; st.w = thi;
                    po[i] = st;                          // STS.128
                }
            } else {
                for (int i = 0; i < len; i++) {
                    const float2 nx = pnx[i];
                    const float4 qp = pqp[i];
                    const float e1lo = y0 + nx.x;
                    const float e1hi = y1 + nx.y;
                    const float hh = e1hi * e1hi;
                    const float sq = fmaf(e1lo, e1lo, hh);
                    const float n1 = sqrta(sq);
                    const float hn = fmaf(hS, n1, ah);
                    ah = A_ * hn;
                    const float thi = th;
                    const float aco = fmaf(mdd, thi, k1);
                    const float r0  = fmaf(thi, qp.x, qp.z);
                    const float r1  = fmaf(thi, qp.y, qp.w);
                    th = tanha(hn);
                    y0 = fmaf(y0, aco, r0);
                    y1 = fmaf(y1, aco, r1);
                    float4 st; st.x = y0; st.y = y1; st.z = n1; st.w = thi;
                    po[i] = st;
                }
            }
            __threadfence_block();
            f_out_ready[slot] = c + 1;
            f_in_done[slot]   = c + 1;
        }
    } else if (wid == 1) {
        // ---------------- producer: GMEM -> SMEM input rings ------------------
        const float g1 = *g1p, g2 = *g2p;
        const float dt = 1.0f / 60.0f;
        const float hg1 = 0.5f * g1,      hg2 = 0.5f * g2;       // raw qh/m
        const float qg1 = dt * hg1,       qg2 = dt * hg2;        // dt-scaled Q/P
        for (int c = 0; c < nchunk; c++) {
            const int slot = c & (NSLOT - 1);
            if (c >= NSLOT) {
                const int need = c - NSLOT + 1;
                while (f_in_done[slot] < need) {}   // serial core done with slot
                while (f_done3[slot]  < need) {}    // warp3 done with s_qm[slot]
            }
            const int base = c * CH;
            const int len  = min(CH, T - base);
            if (len == CH) {
                const float4* g1v4 = (const float4*)(xs1 + (size_t)base * 2);
                const float4* g2v4 = (const float4*)(xs2 + (size_t)base * 2);
                float4* smn = (float4*)s_nx1[slot];
                float4* smp = (float4*)s_qp[slot];
                float4* smm = (float4*)s_qm[slot];
                #pragma unroll
                for (int k = lane; k < CH / 2; k += 32) {   // k covers 2 steps
                    const float4 v1 = __ldg(&g1v4[k]);
                    const float4 v2 = __ldg(&g2v4[k]);
                    float4 n; n.x = -v1.x; n.y = -v1.y; n.z = -v1.z; n.w = -v1.w;
                    smn[k] = n;
                    float4 pa;  // step 2k: {Q0,Q1,P0,P1}
                    pa.x = qg1 * v1.x - qg2 * v2.x;
                    pa.y = qg1 * v1.y - qg2 * v2.y;
                    pa.z = qg1 * v1.x + qg2 * v2.x;
                    pa.w = qg1 * v1.y + qg2 * v2.y;
                    smp[2 * k] = pa;
                    float4 pb;  // step 2k+1
                    pb.x = qg1 * v1.z - qg2 * v2.z;
                    pb.y = qg1 * v1.w - qg2 * v2.w;
                    pb.z = qg1 * v1.z + qg2 * v2.z;
                    pb.w = qg1 * v1.w + qg2 * v2.w;
                    smp[2 * k + 1] = pb;
                    float4 ma;  // step 2k: raw {qh0,qh1,m0,m1}
                    ma.x = hg1 * v1.x - hg2 * v2.x;
                    ma.y = hg1 * v1.y - hg2 * v2.y;
                    ma.z = hg1 * v1.x + hg2 * v2.x;
                    ma.w = hg1 * v1.y + hg2 * v2.y;
                    smm[2 * k] = ma;
                    float4 mb;  // step 2k+1
                    mb.x = hg1 * v1.z - hg2 * v2.z;
                    mb.y = hg1 * v1.w - hg2 * v2.w;
                    mb.z = hg1 * v1.z + hg2 * v2.z;
                    mb.w = hg1 * v1.w + hg2 * v2.w;
                    smm[2 * k + 1] = mb;
                }
            } else {
                for (int k = lane; k < len; k += 32) {
                    const float a0 = xs1[(size_t)(base + k) * 2];
                    const float a1 = xs1[(size_t)(base + k) * 2 + 1];
                    const float b0 = xs2[(size_t)(base + k) * 2];
                    const float b1 = xs2[(size_t)(base + k) * 2 + 1];
                    s_nx1[slot][2 * k]     = -a0;
                    s_nx1[slot][2 * k + 1] = -a1;
                    s_qp[slot][4 * k]     = qg1 * a0 - qg2 * b0;
                    s_qp[slot][4 * k + 1] = qg1 * a1 - qg2 * b1;
                    s_qp[slot][4 * k + 2] = qg1 * a0 + qg2 * b0;
                    s_qp[slot][4 * k + 3] = qg1 * a1 + qg2 * b1;
                    s_qm[slot][4 * k]     = hg1 * a0 - hg2 * b0;
                    s_qm[slot][4 * k + 1] = hg1 * a1 - hg2 * b1;
                    s_qm[slot][4 * k + 2] = hg1 * a0 + hg2 * b0;
                    s_qm[slot][4 * k + 3] = hg1 * a1 + hg2 * b1;
                }
            }
            __threadfence_block();
            __syncwarp();
            if (lane == 0) f_in_ready[slot] = c + 1;
        }
    } else if (wid == 2) {
        // ------- warp2: lane0 x-reconstruct + STG; lanes 1-31 copy y ---------
        const int TP1 = T + 1;
        float A_ = *Ap;
        float s_ = Bp[0] + Bp[1];
        float axr = A_ * (*x0p);               // A*x0 (matches serial seq)
        float* outx = out + 1;                 // x_full[1+t]
        float* outy = out + TP1 + 2;           // y_full[1+t] (ODD: 32-bit only)
        if (lane == 0) {
            out[0]       = *x0p;               // x_full[0]
            out[TP1]     = init_y[0];          // y_full[0]
            out[TP1 + 1] = init_y[1];
        }
        for (int c = 0; c < nchunk; c++) {
            const int slot = c & (NSLOT - 1);
            while (f_out_ready[slot] < c + 1) {}
            __threadfence_block();
            const int base = c * CH;
            const int len  = min(CH, T - base);
            const float* ps = s_out[slot];
            if (lane == 0) {
                for (int i = 0; i < len; i++) {
                    const float n1 = ps[4 * i + 2];
                    const float xn = fmaf(s_, n1, axr);
                    axr = A_ * xn;
                    outx[base + i] = xn;
                }
            } else {
                for (int k = lane - 1; k < len; k += 31) {
                    outy[2 * (size_t)(base + k)]     = ps[4 * k];
                    outy[2 * (size_t)(base + k) + 1] = ps[4 * k + 1];
                }
            }
            __syncwarp();
            if (lane == 0) f_done2[slot] = c + 1;
        }
    } else if (wid == 3) {
        // ------- warp3: lane-parallel EXACT u reconstruction + STG ------------
        // GUARD IS LOAD-BEARING: bare `else` would admit warp0 lanes 1-31,
        // which race the ring and clobber us (R12/R13 failure mode).
        // u_t = fmaf(th_t, fmaf(-d, y_t, qh_t), fmaf(-c, y_t, m_t))
        const int TP1 = T + 1;
        const float g1 = *g1p, g2 = *g2p;
        const float mc  = -0.5f * (g1 + g2);
        const float mdg = -0.5f * (g1 - g2);
        float* outu = out + 3 * TP1;           // us[t] (ODD: 32-bit only)
        float yp0 = init_y[0], yp1 = init_y[1];   // y at chunk start
        for (int c = 0; c < nchunk; c++) {
            const int slot = c & (NSLOT - 1);
            while (f_out_ready[slot] < c + 1) {}
            __threadfence_block();
            const int base = c * CH;
            const int len  = min(CH, T - base);
            const float* ps = s_out[slot];
            const float* pm = s_qm[slot];
            for (int k = lane; k < len; k += 32) {
                float a0, a1;
                if (k == 0) { a0 = yp0; a1 = yp1; }
                else        { a0 = ps[4 * (k - 1)]; a1 = ps[4 * (k - 1) + 1]; }
                const float thk = ps[4 * k + 3];
                const float t0 = fmaf(mdg, a0, pm[4 * k]);
                const float t1 = fmaf(mdg, a1, pm[4 * k + 1]);
                const float p0 = fmaf(mc,  a0, pm[4 * k + 2]);
                const float p1 = fmaf(mc,  a1, pm[4 * k + 3]);
                outu[2 * (size_t)(base + k)]     = fmaf(thk, t0, p0);
                outu[2 * (size_t)(base + k) + 1] = fmaf(thk, t1, p1);
            }
            // carry last y of this chunk (read BEFORE signaling done)
            yp0 = ps[4 * (len - 1)];
            yp1 = ps[4 * (len - 1) + 1];
            __syncwarp();
            if (lane == 0) f_done3[slot] = c + 1;
        }
    }
    // warp0 lanes 1-31: idle after init barrier (no further block-wide syncs).
}

extern "C" void kernel_launch(void* const* d_in, const int* in_sizes, int n_in,
                              void* d_out, int out_size) {
    // Input order (confirmed): [xstar1, xstar2, init_y, x0, A, B, gain1, gain2]
    const float* xs1    = (const float*)d_in[0];
    const float* xs2    = (const float*)d_in[1];
    const float* init_y = (const float*)d_in[2];
    const float* x0     = (const float*)d_in[3];
    const float* A      = (const float*)d_in[4];
    const float* B      = (const float*)d_in[5];
    const float* g1     = (const float*)d_in[6];
    const float* g2     = (const float*)d_in[7];
    const int T = in_sizes[0] / 2;
    LDSMIXTURELQR_58445914964044_kernel<<<1, 128>>>(
        xs1, xs2, init_y, x0, A, B, g1, g2, (float*)d_out, T);
}